// round 13
// baseline (speedup 1.0000x reference)
#include <cuda_runtime.h>
#include <math.h>

#define B_    32
#define NIN   2312
#define NHID  512
#define NOUT  10
#define T_    350
#define TK    100
#define THETA 10.0f

// refractory IIR constants
#define D_REF 0.36787944117144233f
#define C_REF (-5.43656365691809f)

// psp alpha-kernel IIR constants: eps[k] = (e/10) * k * d^k, d = e^{-0.1}
#define D_SR  0.90483741803595952f    // exp(-0.1)
#define C_E   0.27182818284590452f    // e/10
#define K2C   1.2340980408667956e-05f // C_E * exp(-10)
#define K3C   1.2340980408667956e-03f // 100 * C_E * exp(-10)

// sparse index structure
#define NCH   8
#define CHUNK 289
#define CAPC  96
#define NCOL  (B_ * T_)           // 11200

#define R1    (B_ * NHID)         // 16384
#define R2    (B_ * NOUT)         // 320

// ------------------------- static device scratch ---------------------------
__device__ float g_W1T[(size_t)NIN * NHID];                 // [i, o]
__device__ unsigned short g_idx[(size_t)NCOL * NCH * CAPC];
__device__ int            g_cnt[(size_t)NCOL * NCH];
__device__ float g_y1[(size_t)T_ * R1];   // t-major: [t][b*512+o]
__device__ float g_s1[(size_t)T_ * R1];   // t-major
__device__ float g_z2[(size_t)T_ * R2];   // t-major

// ---------------------------------------------------------------------------
// Tiled transpose: W1T[i*512 + o] = W1[o*2312 + i]
// ---------------------------------------------------------------------------
__global__ __launch_bounds__(256) void transpose_w1_kernel(const float* __restrict__ W1) {
    __shared__ float tile[32][33];
    const int i0 = blockIdx.x * 32;
    const int o0 = blockIdx.y * 32;
    const int lx = threadIdx.x & 31;
    const int ly = threadIdx.x >> 5;

#pragma unroll
    for (int r = 0; r < 32; r += 8) {
        int o = o0 + ly + r;
        int i = i0 + lx;
        tile[ly + r][lx] = (i < NIN) ? W1[(size_t)o * NIN + i] : 0.0f;
    }
    __syncthreads();
#pragma unroll
    for (int r = 0; r < 32; r += 8) {
        int i = i0 + ly + r;
        int o = o0 + lx;
        if (i < NIN) g_W1T[(size_t)i * NHID + o] = tile[lx][ly + r];
    }
}

// ---------------------------------------------------------------------------
// Build per-(b,t,chunk) lists of active input indices (coalesced over t).
// ---------------------------------------------------------------------------
__global__ __launch_bounds__(128) void build_idx_kernel(const float* __restrict__ X) {
    const int t = blockIdx.x * 128 + threadIdx.x;
    const int c = blockIdx.y;
    const int b = blockIdx.z;
    if (t >= T_) return;

    const int col = b * T_ + t;
    unsigned short* dst = g_idx + ((size_t)col * NCH + c) * CAPC;
    const float* __restrict__ xb = X + (size_t)b * NIN * T_ + t;

    int cnt = 0;
    const int i0 = c * CHUNK;
#pragma unroll 4
    for (int i = i0; i < i0 + CHUNK; i++) {
        float v = xb[(size_t)i * T_];
        if (v != 0.0f) {
            if (cnt < CAPC) dst[cnt] = (unsigned short)i;
            cnt++;
        }
    }
    g_cnt[col * NCH + c] = (cnt < CAPC) ? cnt : CAPC;
}

// ---------------------------------------------------------------------------
// Sparse gather-accumulate (proven at the L2 roofline):
//   y1T[t][b*512 + :] = sum_{i active(b,t)} W1T[i,:]
// One block per (b,t) column; 128 threads x float4 = 512 outputs.
// ---------------------------------------------------------------------------
__global__ __launch_bounds__(128) void sparse_accum_kernel() {
    const int col = blockIdx.x;
    const int tid = threadIdx.x;

    __shared__ unsigned short sidx[NCH * CAPC];
    __shared__ int psum[NCH + 1];

    if (tid == 0) {
        int s = 0;
        psum[0] = 0;
#pragma unroll
        for (int c = 0; c < NCH; c++) { s += g_cnt[col * NCH + c]; psum[c + 1] = s; }
    }
    __syncthreads();

    if (tid < NCH) {
        const int c = tid;
        const int n = psum[c + 1] - psum[c];
        const unsigned short* src = g_idx + ((size_t)col * NCH + c) * CAPC;
        unsigned short* d = sidx + psum[c];
        for (int k = 0; k < n; k++) d[k] = src[k];
    }
    __syncthreads();

    const int tot = psum[NCH];
    const float4* __restrict__ W = (const float4*)g_W1T;

    float4 acc = make_float4(0.f, 0.f, 0.f, 0.f);
    int k = 0;
    for (; k + 4 <= tot; k += 4) {
        int i0 = sidx[k], i1 = sidx[k + 1], i2 = sidx[k + 2], i3 = sidx[k + 3];
        float4 w0 = W[(size_t)i0 * 128 + tid];
        float4 w1 = W[(size_t)i1 * 128 + tid];
        float4 w2 = W[(size_t)i2 * 128 + tid];
        float4 w3 = W[(size_t)i3 * 128 + tid];
        acc.x += w0.x; acc.y += w0.y; acc.z += w0.z; acc.w += w0.w;
        acc.x += w1.x; acc.y += w1.y; acc.z += w1.z; acc.w += w1.w;
        acc.x += w2.x; acc.y += w2.y; acc.z += w2.z; acc.w += w2.w;
        acc.x += w3.x; acc.y += w3.y; acc.z += w3.z; acc.w += w3.w;
    }
    for (; k < tot; k++) {
        float4 w0 = W[(size_t)sidx[k] * 128 + tid];
        acc.x += w0.x; acc.y += w0.y; acc.z += w0.z; acc.w += w0.w;
    }

    const int b = col / T_;
    const int t = col - b * T_;
    float4* dst = (float4*)(g_y1 + (size_t)t * R1 + b * NHID);
    dst[tid] = acc;   // 128 lanes x float4 = 2KB fully coalesced
}

// ---------------------------------------------------------------------------
// Scan v8: 4 consecutive rows per thread (4 independent IIR chains -> ILP
// hides dependency stalls at 1 warp/SMSP), float4 coalesced LDG/STG on the
// t-major tensors, 5-step double-buffered chunk prefetch.
// 32 threads/block; block covers 128 consecutive rows.
// ---------------------------------------------------------------------------
__global__ __launch_bounds__(32) void iir_scan4_kernel(
    const float* __restrict__ Y, float* __restrict__ Sout)
{
    const int col0 = blockIdx.x * 128 + threadIdx.x * 4;   // first of 4 rows

    float P[4], S[4], P2[4], S2[4], a[4], bst[4];
#pragma unroll
    for (int l = 0; l < 4; l++) { P[l] = S[l] = P2[l] = S2[l] = a[l] = bst[l] = 0.0f; }

    float4 yv[5], yo[5], nyv[5], nyo[5];

    // preload chunk 0 (t = 0..4)
#pragma unroll
    for (int k = 0; k < 5; k++)
        yv[k] = *(const float4*)(Y + (size_t)k * R1 + col0);
#pragma unroll
    for (int k = 0; k < 5; k++) yo[k] = make_float4(0.f, 0.f, 0.f, 0.f);

#pragma unroll 1
    for (int c = 0; c < 70; c++) {
        const int t0 = c * 5;

        // prefetch chunk c+1
        if (c < 69) {
            const int tn = t0 + 5;
#pragma unroll
            for (int k = 0; k < 5; k++)
                nyv[k] = *(const float4*)(Y + (size_t)(tn + k) * R1 + col0);
            if (c + 1 >= 20) {
#pragma unroll
                for (int k = 0; k < 5; k++)
                    nyo[k] = *(const float4*)(Y + (size_t)(tn + k - TK) * R1 + col0);
            } else {
#pragma unroll
                for (int k = 0; k < 5; k++) nyo[k] = make_float4(0.f, 0.f, 0.f, 0.f);
            }
        }

        // compute 5 steps x 4 independent rows
#pragma unroll
        for (int k = 0; k < 5; k++) {
            const float yvk[4] = {yv[k].x, yv[k].y, yv[k].z, yv[k].w};
            const float yok[4] = {yo[k].x, yo[k].y, yo[k].z, yo[k].w};
            float sk[4];
#pragma unroll
            for (int l = 0; l < 4; l++) {
                const float dP2 = D_SR * P2[l];
                S2[l] = fmaf(D_SR, S2[l], dP2);
                P2[l] = dP2 + yok[l];
                const float corr = fmaf(-K2C, S2[l], -K3C * P2[l]);

                const float dP = D_SR * P[l];
                S[l] = fmaf(D_SR, S[l], dP);
                P[l] = dP + yvk[l];

                const float u = fmaf(C_E, S[l], fmaf(C_REF, bst[l], corr));
                const float s = (u >= THETA) ? 1.0f : 0.0f;
                const float g = D_REF * a[l];
                bst[l] = fmaf(D_REF, bst[l], g);
                a[l]   = g + s;
                sk[l]  = s;
            }
            *(float4*)(Sout + (size_t)(t0 + k) * R1 + col0) =
                make_float4(sk[0], sk[1], sk[2], sk[3]);
        }

        // rotate
#pragma unroll
        for (int k = 0; k < 5; k++) { yv[k] = nyv[k]; yo[k] = nyo[k]; }
    }
}

// ---------------------------------------------------------------------------
// Scan v6 scalar (kept for the tiny layer-2): t-major in, row-major out.
// ---------------------------------------------------------------------------
__global__ __launch_bounds__(64) void iir_scan2_kernel(
    const float* __restrict__ Y, float* __restrict__ Sout)
{
    const int row = blockIdx.x * 64 + threadIdx.x;
    const float* __restrict__ yp = Y + row;

    float P = 0.f, S = 0.f, P2 = 0.f, S2 = 0.f, a = 0.f, bst = 0.f;
    float yv[10], yo[10], nyv[10], nyo[10], sbf[10];

#pragma unroll
    for (int k = 0; k < 10; k++) yv[k] = yp[(size_t)k * R2];
#pragma unroll
    for (int k = 0; k < 10; k++) yo[k] = 0.0f;

    for (int c = 0; c < 35; c++) {
        const int t0 = c * 10;
        if (c < 34) {
            const int tn = t0 + 10;
#pragma unroll
            for (int k = 0; k < 10; k++) nyv[k] = yp[(size_t)(tn + k) * R2];
            if (c + 1 >= 10) {
#pragma unroll
                for (int k = 0; k < 10; k++) nyo[k] = yp[(size_t)(tn + k - TK) * R2];
            } else {
#pragma unroll
                for (int k = 0; k < 10; k++) nyo[k] = 0.0f;
            }
        }
#pragma unroll
        for (int k = 0; k < 10; k++) {
            const float dP2 = D_SR * P2;
            S2 = fmaf(D_SR, S2, dP2);
            P2 = dP2 + yo[k];
            const float corr = fmaf(-K2C, S2, -K3C * P2);

            const float dP = D_SR * P;
            S = fmaf(D_SR, S, dP);
            P = dP + yv[k];

            const float u = fmaf(C_E, S, fmaf(C_REF, bst, corr));
            const float s = (u >= THETA) ? 1.0f : 0.0f;
            const float g = D_REF * a;
            bst = fmaf(D_REF, bst, g);
            a   = g + s;
            sbf[k] = s;
        }
#pragma unroll
        for (int k = 0; k < 10; k++)
            Sout[(size_t)row * T_ + t0 + k] = sbf[k];
#pragma unroll
        for (int k = 0; k < 10; k++) { yv[k] = nyv[k]; yo[k] = nyo[k]; }
    }
}

// ---------------------------------------------------------------------------
// GEMM2 on t-major s1: warp per (b,t) column.
// ---------------------------------------------------------------------------
__global__ __launch_bounds__(256) void gemm2_kernel(
    const float* __restrict__ W2, const float* __restrict__ S1T,
    float* __restrict__ Z2T)
{
    __shared__ float w2s[NOUT * NHID];
    for (int i = threadIdx.x; i < NOUT * NHID; i += 256) w2s[i] = W2[i];
    __syncthreads();

    const int warp = threadIdx.x >> 5;
    const int lane = threadIdx.x & 31;
    const int col  = blockIdx.x * 8 + warp;
    const int b    = col / T_;
    const int t    = col - b * T_;

    const float4* __restrict__ sv = (const float4*)(S1T + (size_t)t * R1 + b * NHID);
    const float4* __restrict__ wv = (const float4*)w2s;

    float acc[NOUT];
#pragma unroll
    for (int j = 0; j < NOUT; j++) acc[j] = 0.0f;

#pragma unroll
    for (int p = 0; p < 4; p++) {
        float4 v = sv[p * 32 + lane];
#pragma unroll
        for (int j = 0; j < NOUT; j++) {
            float4 w = wv[j * 128 + p * 32 + lane];
            acc[j] += w.x * v.x + w.y * v.y + w.z * v.z + w.w * v.w;
        }
    }

#pragma unroll
    for (int j = 0; j < NOUT; j++) {
#pragma unroll
        for (int sh = 16; sh > 0; sh >>= 1)
            acc[j] += __shfl_xor_sync(0xffffffffu, acc[j], sh);
    }

    if (lane < NOUT)
        Z2T[(size_t)t * R2 + b * NOUT + lane] = acc[lane];
}

// ---------------------------------------------------------------------------
extern "C" void kernel_launch(void* const* d_in, const int* in_sizes, int n_in,
                              void* d_out, int out_size)
{
    const float* spikeInput = (const float*)d_in[0];  // [32, 2312, 350]
    const float* W1         = (const float*)d_in[1];  // [512, 2312]
    const float* W2         = (const float*)d_in[2];  // [10, 512]
    float*       out        = (float*)d_out;          // [32, 10, 350]

    float *y1p, *s1p, *z2p;
    cudaGetSymbolAddress((void**)&y1p, g_y1);
    cudaGetSymbolAddress((void**)&s1p, g_s1);
    cudaGetSymbolAddress((void**)&z2p, g_z2);

    dim3 gt((NIN + 31) / 32, NHID / 32);      // (73, 16)
    transpose_w1_kernel<<<gt, 256>>>(W1);

    dim3 gb((T_ + 127) / 128, NCH, B_);       // (3, 8, 32)
    build_idx_kernel<<<gb, 128>>>(spikeInput);

    sparse_accum_kernel<<<NCOL, 128>>>();

    iir_scan4_kernel<<<R1 / 128, 32>>>(y1p, s1p);   // launch #4 (profiled)

    gemm2_kernel<<<NCOL / 8, 256>>>(W2, s1p, z2p);

    iir_scan2_kernel<<<R2 / 64, 64>>>(z2p, out);
}

// round 14
// speedup vs baseline: 1.0558x; 1.0558x over previous
#include <cuda_runtime.h>
#include <math.h>

#define B_    32
#define NIN   2312
#define NHID  512
#define NOUT  10
#define T_    350
#define TK    100
#define THETA 10.0f

// refractory IIR constants
#define D_REF 0.36787944117144233f
#define C_REF (-5.43656365691809f)

// psp alpha-kernel IIR constants: eps[k] = (e/10) * k * d^k, d = e^{-0.1}
#define D_SR  0.90483741803595952f    // exp(-0.1)
#define C_E   0.27182818284590452f    // e/10
#define K2C   1.2340980408667956e-05f // C_E * exp(-10)
#define K3C   1.2340980408667956e-03f // 100 * C_E * exp(-10)

// sparse index structure
#define NCH   8
#define CHUNK 289
#define CAPC  96
#define NCOL  (B_ * T_)           // 11200

#define R1    (B_ * NHID)         // 16384
#define R2    (B_ * NOUT)         // 320

// fused prep kernel geometry
#define NTRB  (73 * 16)           // 1168 transpose tiles
#define NBLB  (2 * NCH * B_)      // 512 build blocks (2 t-segments x 8 chunks x 32 b)

// ------------------------- static device scratch ---------------------------
__device__ float g_W1T[(size_t)NIN * NHID];                 // [i, o]
__device__ unsigned short g_idx[(size_t)NCOL * NCH * CAPC];
__device__ int            g_cnt[(size_t)NCOL * NCH];
__device__ float g_y1[(size_t)T_ * R1];   // t-major: [t][b*512+o]
__device__ float g_s1[(size_t)T_ * R1];   // t-major
__device__ float g_z2[(size_t)T_ * R2];   // t-major

// ---------------------------------------------------------------------------
// Fused prep: W1 transpose tiles (blocks [0, 1168)) + active-index build
// (blocks [1168, 1168+512)). The two tasks are independent; fusing them
// overlaps the transpose with the build inside one wave.
// ---------------------------------------------------------------------------
__global__ __launch_bounds__(256) void prep_kernel(
    const float* __restrict__ W1, const float* __restrict__ X)
{
    const int bid = blockIdx.x;

    if (bid < NTRB) {
        // ---- transpose tile: W1T[i*512 + o] = W1[o*2312 + i] ----
        __shared__ float tile[32][33];
        const int i0 = (bid % 73) * 32;
        const int o0 = (bid / 73) * 32;
        const int lx = threadIdx.x & 31;
        const int ly = threadIdx.x >> 5;   // 0..7

#pragma unroll
        for (int r = 0; r < 32; r += 8) {
            int o = o0 + ly + r;
            int i = i0 + lx;
            tile[ly + r][lx] = (i < NIN) ? W1[(size_t)o * NIN + i] : 0.0f;
        }
        __syncthreads();
#pragma unroll
        for (int r = 0; r < 32; r += 8) {
            int i = i0 + ly + r;
            int o = o0 + lx;
            if (i < NIN) g_W1T[(size_t)i * NHID + o] = tile[lx][ly + r];
        }
    } else {
        // ---- build: per-(b,t,chunk) active input index lists ----
        const int bid2 = bid - NTRB;
        const int tseg = bid2 & 1;
        const int c    = (bid2 >> 1) & 7;
        const int b    = bid2 >> 4;
        const int t    = tseg * 256 + threadIdx.x;
        if (t >= T_) return;

        const int col = b * T_ + t;
        unsigned short* dst = g_idx + ((size_t)col * NCH + c) * CAPC;
        const float* __restrict__ xb = X + (size_t)b * NIN * T_ + t;

        int cnt = 0;
        const int i0 = c * CHUNK;
#pragma unroll 4
        for (int i = i0; i < i0 + CHUNK; i++) {
            float v = xb[(size_t)i * T_];
            if (v != 0.0f) {
                if (cnt < CAPC) dst[cnt] = (unsigned short)i;
                cnt++;
            }
        }
        g_cnt[col * NCH + c] = (cnt < CAPC) ? cnt : CAPC;
    }
}

// ---------------------------------------------------------------------------
// Sparse gather-accumulate (proven at the L1/L2 roofline):
//   y1T[t][b*512 + :] = sum_{i active(b,t)} W1T[i,:]
// One block per (b,t) column; 128 threads x float4 = 512 outputs.
// ---------------------------------------------------------------------------
__global__ __launch_bounds__(128) void sparse_accum_kernel() {
    const int col = blockIdx.x;
    const int tid = threadIdx.x;

    __shared__ unsigned short sidx[NCH * CAPC];
    __shared__ int psum[NCH + 1];

    if (tid == 0) {
        int s = 0;
        psum[0] = 0;
#pragma unroll
        for (int c = 0; c < NCH; c++) { s += g_cnt[col * NCH + c]; psum[c + 1] = s; }
    }
    __syncthreads();

    if (tid < NCH) {
        const int c = tid;
        const int n = psum[c + 1] - psum[c];
        const unsigned short* src = g_idx + ((size_t)col * NCH + c) * CAPC;
        unsigned short* d = sidx + psum[c];
        for (int k = 0; k < n; k++) d[k] = src[k];
    }
    __syncthreads();

    const int tot = psum[NCH];
    const float4* __restrict__ W = (const float4*)g_W1T;

    float4 acc = make_float4(0.f, 0.f, 0.f, 0.f);
    int k = 0;
    for (; k + 4 <= tot; k += 4) {
        int i0 = sidx[k], i1 = sidx[k + 1], i2 = sidx[k + 2], i3 = sidx[k + 3];
        float4 w0 = W[(size_t)i0 * 128 + tid];
        float4 w1 = W[(size_t)i1 * 128 + tid];
        float4 w2 = W[(size_t)i2 * 128 + tid];
        float4 w3 = W[(size_t)i3 * 128 + tid];
        acc.x += w0.x; acc.y += w0.y; acc.z += w0.z; acc.w += w0.w;
        acc.x += w1.x; acc.y += w1.y; acc.z += w1.z; acc.w += w1.w;
        acc.x += w2.x; acc.y += w2.y; acc.z += w2.z; acc.w += w2.w;
        acc.x += w3.x; acc.y += w3.y; acc.z += w3.z; acc.w += w3.w;
    }
    for (; k < tot; k++) {
        float4 w0 = W[(size_t)sidx[k] * 128 + tid];
        acc.x += w0.x; acc.y += w0.y; acc.z += w0.z; acc.w += w0.w;
    }

    const int b = col / T_;
    const int t = col - b * T_;
    float4* dst = (float4*)(g_y1 + (size_t)t * R1 + b * NHID);
    dst[tid] = acc;   // 128 lanes x float4 = 2KB fully coalesced
}

// ---------------------------------------------------------------------------
// Scan v6 (proven): t-major, compile-time stride, double-buffered chunk
// prefetch. psp IIR + exact TK=100 truncation correction via second IIR on
// y[t-100] + threshold/refractory scan. One thread per row.
// ---------------------------------------------------------------------------
template<int STRIDE, bool TMAJOR_OUT>
__global__ __launch_bounds__(64) void iir_scan_kernel(
    const float* __restrict__ Y, float* __restrict__ Sout)
{
    const int row = blockIdx.x * 64 + threadIdx.x;
    const float* __restrict__ yp = Y + row;

    float P = 0.f, S = 0.f;       // psp states
    float P2 = 0.f, S2 = 0.f;     // delayed psp states
    float a = 0.f, bst = 0.f;     // refractory states

    float yv[10], yo[10], nyv[10], nyo[10], sb[10];

    // preload chunk 0
#pragma unroll
    for (int k = 0; k < 10; k++) yv[k] = yp[(size_t)k * STRIDE];
#pragma unroll
    for (int k = 0; k < 10; k++) yo[k] = 0.0f;

    for (int c = 0; c < 35; c++) {
        const int t0 = c * 10;

        // prefetch chunk c+1 (overlaps with compute below)
        if (c < 34) {
            const int tn = t0 + 10;
#pragma unroll
            for (int k = 0; k < 10; k++)
                nyv[k] = yp[(size_t)(tn + k) * STRIDE];
            if (c + 1 >= 10) {
#pragma unroll
                for (int k = 0; k < 10; k++)
                    nyo[k] = yp[(size_t)(tn + k - TK) * STRIDE];
            } else {
#pragma unroll
                for (int k = 0; k < 10; k++) nyo[k] = 0.0f;
            }
        }

        // compute chunk c
#pragma unroll
        for (int k = 0; k < 10; k++) {
            const float dP2 = D_SR * P2;
            S2 = fmaf(D_SR, S2, dP2);
            P2 = dP2 + yo[k];
            const float corr = fmaf(-K2C, S2, -K3C * P2);

            const float dP = D_SR * P;
            S = fmaf(D_SR, S, dP);
            P = dP + yv[k];

            const float u = fmaf(C_E, S, fmaf(C_REF, bst, corr));
            const float s = (u >= THETA) ? 1.0f : 0.0f;
            const float g = D_REF * a;
            bst = fmaf(D_REF, bst, g);
            a   = g + s;
            sb[k] = s;
        }

        if (TMAJOR_OUT) {
#pragma unroll
            for (int k = 0; k < 10; k++)
                Sout[(size_t)(t0 + k) * STRIDE + row] = sb[k];
        } else {
#pragma unroll
            for (int k = 0; k < 10; k++)
                Sout[(size_t)row * T_ + t0 + k] = sb[k];
        }

        // rotate buffers
#pragma unroll
        for (int k = 0; k < 10; k++) { yv[k] = nyv[k]; yo[k] = nyo[k]; }
    }
}

// ---------------------------------------------------------------------------
// GEMM2 on t-major s1: warp per (b,t) column.
// ---------------------------------------------------------------------------
__global__ __launch_bounds__(256) void gemm2_kernel(
    const float* __restrict__ W2, const float* __restrict__ S1T,
    float* __restrict__ Z2T)
{
    __shared__ float w2s[NOUT * NHID];
    for (int i = threadIdx.x; i < NOUT * NHID; i += 256) w2s[i] = W2[i];
    __syncthreads();

    const int warp = threadIdx.x >> 5;
    const int lane = threadIdx.x & 31;
    const int col  = blockIdx.x * 8 + warp;
    const int b    = col / T_;
    const int t    = col - b * T_;

    const float4* __restrict__ sv = (const float4*)(S1T + (size_t)t * R1 + b * NHID);
    const float4* __restrict__ wv = (const float4*)w2s;

    float acc[NOUT];
#pragma unroll
    for (int j = 0; j < NOUT; j++) acc[j] = 0.0f;

#pragma unroll
    for (int p = 0; p < 4; p++) {
        float4 v = sv[p * 32 + lane];
#pragma unroll
        for (int j = 0; j < NOUT; j++) {
            float4 w = wv[j * 128 + p * 32 + lane];
            acc[j] += w.x * v.x + w.y * v.y + w.z * v.z + w.w * v.w;
        }
    }

#pragma unroll
    for (int j = 0; j < NOUT; j++) {
#pragma unroll
        for (int sh = 16; sh > 0; sh >>= 1)
            acc[j] += __shfl_xor_sync(0xffffffffu, acc[j], sh);
    }

    if (lane < NOUT)
        Z2T[(size_t)t * R2 + b * NOUT + lane] = acc[lane];
}

// ---------------------------------------------------------------------------
extern "C" void kernel_launch(void* const* d_in, const int* in_sizes, int n_in,
                              void* d_out, int out_size)
{
    const float* spikeInput = (const float*)d_in[0];  // [32, 2312, 350]
    const float* W1         = (const float*)d_in[1];  // [512, 2312]
    const float* W2         = (const float*)d_in[2];  // [10, 512]
    float*       out        = (float*)d_out;          // [32, 10, 350]

    float *y1p, *s1p, *z2p;
    cudaGetSymbolAddress((void**)&y1p, g_y1);
    cudaGetSymbolAddress((void**)&s1p, g_s1);
    cudaGetSymbolAddress((void**)&z2p, g_z2);

    // #1: fused transpose + index build
    prep_kernel<<<NTRB + NBLB, 256>>>(W1, spikeInput);

    // #2: sparse gather-accumulate (the dominant kernel)
    sparse_accum_kernel<<<NCOL, 128>>>();

    // #3: layer-1 scan
    iir_scan_kernel<R1, true><<<R1 / 64, 64>>>(y1p, s1p);

    // #4: dense layer 2
    gemm2_kernel<<<NCOL / 8, 256>>>(W2, s1p, z2p);

    // #5: layer-2 scan -> final output
    iir_scan_kernel<R2, false><<<R2 / 64, 64>>>(z2p, out);
}